// round 2
// baseline (speedup 1.0000x reference)
#include <cuda_runtime.h>
#include <math.h>
#include <stdint.h>

// Problem constants
#define B_    4
#define L_    2048
#define E_    1024
#define H_    16
#define DK_   64
#define MTOK  (B_ * L_)          // 8192
#define QKV_N (3 * H_ * DK_)     // 3072
#define HD_   (H_ * DK_)         // 1024

// Scratch (allocation-free rule)
__device__ float g_qkv[(size_t)MTOK * QKV_N];
__device__ float g_att[(size_t)MTOK * HD_];

// ---------------------------------------------------------------------------
// TF32 helpers
// ---------------------------------------------------------------------------
__device__ __forceinline__ uint32_t f2tf(float x) {
    uint32_t u;
    asm("cvt.rna.tf32.f32 %0, %1;" : "=r"(u) : "f"(x));
    return u;
}

__device__ __forceinline__ void mma8(float* c, const uint32_t* a, const uint32_t* b) {
    asm volatile(
        "mma.sync.aligned.m16n8k8.row.col.f32.tf32.tf32.f32 "
        "{%0,%1,%2,%3},{%4,%5,%6,%7},{%8,%9},{%0,%1,%2,%3};"
        : "+f"(c[0]), "+f"(c[1]), "+f"(c[2]), "+f"(c[3])
        : "r"(a[0]), "r"(a[1]), "r"(a[2]), "r"(a[3]), "r"(b[0]), "r"(b[1]));
}

// Fragment-order smem layouts:
// A-region (16-row m-tiles x 8-col k-steps):
//   word = ((mtile*KS + kstep)*32 + (r16&7)*4 + (c&3))*4 + ((c8>=4)?2:0) + (r16>=8)
//   -> per (mtile,kstep) each lane's 4 A-regs are one contiguous uint4.
// B-region (8k x 8n tiles):
//   word = ((ntile*KS + kstep)*32 + n8*4 + (k8&3))*2 + (k8>=4)
//   -> per (ntile,kstep) each lane's 2 B-regs are one contiguous uint2.

// ---------------------------------------------------------------------------
// GEMM: C[M,N] = A[M,K] @ B[K,N] + bias, split-tf32 (3xTF32).
// 128x128 block tile, BK=32, 256 threads = 8 warps (2 m x 4 n), warp 64x32.
// Dynamic smem 64KB: Ah,Al (4096 words each), Bh,Bl (4096 words each).
// ---------------------------------------------------------------------------
__global__ __launch_bounds__(256, 2) void gemm_tf32x3(
    const float* __restrict__ A, const float* __restrict__ Bm,
    const float* __restrict__ bias, float* __restrict__ C,
    int M, int N, int K)
{
    extern __shared__ uint32_t sg[];
    uint32_t* Ah = sg;
    uint32_t* Al = Ah + 4096;
    uint32_t* Bh = Al + 4096;
    uint32_t* Bl = Bh + 4096;

    const int tid = threadIdx.x, lane = tid & 31, warp = tid >> 5;
    const int wm = warp & 1, wn = warp >> 1;
    const int brow = blockIdx.y * 128, bcol = blockIdx.x * 128;

    float acc[4][4][4] = {};

    const int ar = tid >> 3;          // A: row 0..31 (+32 strides)
    const int ac = (tid & 7) * 4;     // A: k col
    const int bk = tid >> 5;          // B: k row 0..7 (+8 strides)
    const int bc = (tid & 31) * 4;    // B: n col

    for (int k0 = 0; k0 < K; k0 += 32) {
        // ---- stage A tile 128x32 into fragment order ----
        #pragma unroll
        for (int rr = 0; rr < 4; ++rr) {
            const int r = ar + rr * 32;
            float4 v = *(const float4*)(A + (size_t)(brow + r) * K + k0 + ac);
            float xs[4] = {v.x, v.y, v.z, v.w};
            const int mtile = r >> 4, r16 = r & 15;
            const int lb = (r16 & 7) * 4, regr = (r16 >= 8) ? 1 : 0;
            #pragma unroll
            for (int i = 0; i < 4; ++i) {
                const int c = ac + i, kstep = c >> 3, c8 = c & 7;
                const int idx = ((mtile * 4 + kstep) * 32 + lb + (c & 3)) * 4
                              + ((c8 >= 4) ? 2 : 0) + regr;
                const uint32_t hb = f2tf(xs[i]);
                Ah[idx] = hb;
                Al[idx] = f2tf(xs[i] - __uint_as_float(hb));
            }
        }
        // ---- stage B tile 32x128 ----
        #pragma unroll
        for (int rr = 0; rr < 4; ++rr) {
            const int k = bk + rr * 8;
            float4 v = *(const float4*)(Bm + (size_t)(k0 + k) * N + bcol + bc);
            float xs[4] = {v.x, v.y, v.z, v.w};
            const int kstep = k >> 3, k8 = k & 7;
            const int reg = (k8 >= 4) ? 1 : 0;
            #pragma unroll
            for (int i = 0; i < 4; ++i) {
                const int col = bc + i, ntile = col >> 3, n8 = col & 7;
                const int idx = ((ntile * 4 + kstep) * 32 + n8 * 4 + (k8 & 3)) * 2 + reg;
                const uint32_t hb = f2tf(xs[i]);
                Bh[idx] = hb;
                Bl[idx] = f2tf(xs[i] - __uint_as_float(hb));
            }
        }
        __syncthreads();

        #pragma unroll
        for (int ks = 0; ks < 4; ++ks) {
            uint32_t aH[4][4], aL[4][4], bH[4][2], bL[4][2];
            #pragma unroll
            for (int mi = 0; mi < 4; ++mi) {
                const int base = (((wm * 4 + mi) * 4 + ks) * 32 + lane) * 4;
                *(uint4*)aH[mi] = *(const uint4*)&Ah[base];
                *(uint4*)aL[mi] = *(const uint4*)&Al[base];
            }
            #pragma unroll
            for (int nj = 0; nj < 4; ++nj) {
                const int base = (((wn * 4 + nj) * 4 + ks) * 32 + lane) * 2;
                *(uint2*)bH[nj] = *(const uint2*)&Bh[base];
                *(uint2*)bL[nj] = *(const uint2*)&Bl[base];
            }
            #pragma unroll
            for (int mi = 0; mi < 4; ++mi)
                #pragma unroll
                for (int nj = 0; nj < 4; ++nj) {
                    mma8(acc[mi][nj], aH[mi], bH[nj]);
                    mma8(acc[mi][nj], aH[mi], bL[nj]);
                    mma8(acc[mi][nj], aL[mi], bH[nj]);
                }
        }
        __syncthreads();
    }

    // epilogue: C fragment c0,c1=(r,2c),(r,2c+1); c2,c3=(r+8,...)
    #pragma unroll
    for (int mi = 0; mi < 4; ++mi) {
        const int row = brow + wm * 64 + mi * 16 + (lane >> 2);
        #pragma unroll
        for (int nj = 0; nj < 4; ++nj) {
            const int col = bcol + wn * 32 + nj * 8 + 2 * (lane & 3);
            const float b0 = __ldg(&bias[col]), b1 = __ldg(&bias[col + 1]);
            float2 v0 = {acc[mi][nj][0] + b0, acc[mi][nj][1] + b1};
            float2 v1 = {acc[mi][nj][2] + b0, acc[mi][nj][3] + b1};
            *(float2*)(C + (size_t)row * N + col) = v0;
            *(float2*)(C + (size_t)(row + 8) * N + col) = v1;
        }
    }
}

// ---------------------------------------------------------------------------
// Flash attention, split-tf32 mma. Grid (L/128, H, B), 256 threads = 8 warps.
// Warp w owns q rows [16w,16w+16) of the 128-query block; key chunks of 32.
// Dynamic smem 128KB.
// ---------------------------------------------------------------------------
#define CH 32

__global__ __launch_bounds__(256) void attn_tf32x3(
    const float* __restrict__ qkv, float* __restrict__ att)
{
    extern __shared__ uint32_t sa[];
    uint32_t* Qh = sa;            // 8 mtiles * 8 ksteps * 32 * 4 = 8192 words
    uint32_t* Ql = Qh + 8192;
    uint32_t* Kh = Ql + 8192;     // 4 ntiles * 8 ksteps * 32 * 2 = 2048
    uint32_t* Kl = Kh + 2048;
    uint32_t* Vh = Kl + 2048;     // 8 ntiles * 4 ksteps * 32 * 2 = 2048
    uint32_t* Vl = Vh + 2048;
    uint32_t* Ph = Vl + 2048;     // 8 warps * (4 ksteps * 32 * 4) = 4096
    uint32_t* Pl = Ph + 4096;     // total 32768 words = 128KB

    const int b = blockIdx.z, h = blockIdx.y, q0 = blockIdx.x * 128;
    const int tid = threadIdx.x, lane = tid & 31, warp = tid >> 5;
    const size_t base = ((size_t)b * L_) * QKV_N + (size_t)h * (3 * DK_);

    // ---- stage Q 128x64 into A-fragment order (KS=8) ----
    for (int t = tid; t < 128 * 16; t += 256) {
        const int q = t >> 4, d4 = (t & 15) << 2;
        float4 v = *(const float4*)(qkv + base + (size_t)(q0 + q) * QKV_N + d4);
        float xs[4] = {v.x, v.y, v.z, v.w};
        const int mtile = q >> 4, r16 = q & 15;
        const int lb = (r16 & 7) * 4, regr = (r16 >= 8) ? 1 : 0;
        #pragma unroll
        for (int i = 0; i < 4; ++i) {
            const int d = d4 + i, kstep = d >> 3, c8 = d & 7;
            const int idx = ((mtile * 8 + kstep) * 32 + lb + (d & 3)) * 4
                          + ((c8 >= 4) ? 2 : 0) + regr;
            const uint32_t hb = f2tf(xs[i]);
            Qh[idx] = hb;
            Ql[idx] = f2tf(xs[i] - __uint_as_float(hb));
        }
    }

    float oacc[8][4] = {};
    float m0 = -INFINITY, m1 = -INFINITY, l0 = 0.f, l1 = 0.f;
    const float scale = 0.125f;   // 1/sqrt(64)

    for (int kc = 0; kc < L_; kc += CH) {
        __syncthreads();   // protects K/V/P smem reuse across chunks
        // ---- stage K,V chunk 32x64 each ----
        for (int t = tid; t < CH * 16; t += 256) {
            const int j = t >> 4, d4 = (t & 15) << 2;
            const float* rp = qkv + base + (size_t)(kc + j) * QKV_N;
            float4 kv = *(const float4*)(rp + DK_ + d4);
            float4 vv = *(const float4*)(rp + 2 * DK_ + d4);
            float ks_[4] = {kv.x, kv.y, kv.z, kv.w};
            float vs_[4] = {vv.x, vv.y, vv.z, vv.w};
            #pragma unroll
            for (int i = 0; i < 4; ++i) {
                const int d = d4 + i;
                // K: B-layout for S (n=key j, k=d, KS=8)
                const int idxK = (((j >> 3) * 8 + (d >> 3)) * 32 + (j & 7) * 4 + (d & 3)) * 2
                               + (((d & 7) >= 4) ? 1 : 0);
                uint32_t hb = f2tf(ks_[i]);
                Kh[idxK] = hb;
                Kl[idxK] = f2tf(ks_[i] - __uint_as_float(hb));
                // V: B-layout for PV (n=d, k=key j, KS=4)
                const int idxV = (((d >> 3) * 4 + (j >> 3)) * 32 + (d & 7) * 4 + (j & 3)) * 2
                               + (((j & 7) >= 4) ? 1 : 0);
                uint32_t hv = f2tf(vs_[i]);
                Vh[idxV] = hv;
                Vl[idxV] = f2tf(vs_[i] - __uint_as_float(hv));
            }
        }
        __syncthreads();

        // ---- S = Q K^T : warp's 16 q-rows x 32 keys ----
        float sacc[4][4] = {};
        #pragma unroll
        for (int ks = 0; ks < 8; ++ks) {
            uint32_t aH[4], aL[4];
            const int ab = ((warp * 8 + ks) * 32 + lane) * 4;
            *(uint4*)aH = *(const uint4*)&Qh[ab];
            *(uint4*)aL = *(const uint4*)&Ql[ab];
            #pragma unroll
            for (int nj = 0; nj < 4; ++nj) {
                uint32_t bH[2], bL[2];
                const int bb = ((nj * 8 + ks) * 32 + lane) * 2;
                *(uint2*)bH = *(const uint2*)&Kh[bb];
                *(uint2*)bL = *(const uint2*)&Kl[bb];
                mma8(sacc[nj], aH, bH);
                mma8(sacc[nj], aH, bL);
                mma8(sacc[nj], aL, bH);
            }
        }

        // ---- online softmax (row0 = regs 0,1; row1 = regs 2,3) ----
        {
            float mloc = -INFINITY;
            #pragma unroll
            for (int nj = 0; nj < 4; ++nj) {
                sacc[nj][0] *= scale; sacc[nj][1] *= scale;
                mloc = fmaxf(mloc, fmaxf(sacc[nj][0], sacc[nj][1]));
            }
            mloc = fmaxf(mloc, __shfl_xor_sync(0xffffffffu, mloc, 1));
            mloc = fmaxf(mloc, __shfl_xor_sync(0xffffffffu, mloc, 2));
            const float mnew = fmaxf(m0, mloc);
            const float corr = __expf(m0 - mnew);
            m0 = mnew;
            float lsum = 0.f;
            #pragma unroll
            for (int nj = 0; nj < 4; ++nj) {
                float p0 = __expf(sacc[nj][0] - mnew);
                float p1 = __expf(sacc[nj][1] - mnew);
                sacc[nj][0] = p0; sacc[nj][1] = p1;
                lsum += p0 + p1;
            }
            lsum += __shfl_xor_sync(0xffffffffu, lsum, 1);
            lsum += __shfl_xor_sync(0xffffffffu, lsum, 2);
            l0 = l0 * corr + lsum;
            #pragma unroll
            for (int nj = 0; nj < 8; ++nj) { oacc[nj][0] *= corr; oacc[nj][1] *= corr; }
        }
        {
            float mloc = -INFINITY;
            #pragma unroll
            for (int nj = 0; nj < 4; ++nj) {
                sacc[nj][2] *= scale; sacc[nj][3] *= scale;
                mloc = fmaxf(mloc, fmaxf(sacc[nj][2], sacc[nj][3]));
            }
            mloc = fmaxf(mloc, __shfl_xor_sync(0xffffffffu, mloc, 1));
            mloc = fmaxf(mloc, __shfl_xor_sync(0xffffffffu, mloc, 2));
            const float mnew = fmaxf(m1, mloc);
            const float corr = __expf(m1 - mnew);
            m1 = mnew;
            float lsum = 0.f;
            #pragma unroll
            for (int nj = 0; nj < 4; ++nj) {
                float p0 = __expf(sacc[nj][2] - mnew);
                float p1 = __expf(sacc[nj][3] - mnew);
                sacc[nj][2] = p0; sacc[nj][3] = p1;
                lsum += p0 + p1;
            }
            lsum += __shfl_xor_sync(0xffffffffu, lsum, 1);
            lsum += __shfl_xor_sync(0xffffffffu, lsum, 2);
            l1 = l1 * corr + lsum;
            #pragma unroll
            for (int nj = 0; nj < 8; ++nj) { oacc[nj][2] *= corr; oacc[nj][3] *= corr; }
        }

        // ---- write P into per-warp A-fragment region (KS=4) ----
        {
            const int r0 = lane >> 2, cb = 2 * (lane & 3);
            uint32_t* PHW = Ph + warp * 512;
            uint32_t* PLW = Pl + warp * 512;
            #pragma unroll
            for (int nj = 0; nj < 4; ++nj)
                #pragma unroll
                for (int v = 0; v < 4; ++v) {
                    const int row = r0 + ((v >= 2) ? 8 : 0);
                    const int col = nj * 8 + cb + (v & 1);
                    const int idx = ((col >> 3) * 32 + (row & 7) * 4 + (col & 3)) * 4
                                  + (((col & 7) >= 4) ? 2 : 0) + ((row >= 8) ? 1 : 0);
                    const float p = sacc[nj][v];
                    const uint32_t hb = f2tf(p);
                    PHW[idx] = hb;
                    PLW[idx] = f2tf(p - __uint_as_float(hb));
                }
        }
        __syncwarp();

        // ---- O += P V ----
        #pragma unroll
        for (int ks = 0; ks < 4; ++ks) {
            uint32_t aH[4], aL[4];
            const int ab = warp * 512 + (ks * 32 + lane) * 4;
            *(uint4*)aH = *(const uint4*)&Ph[ab];
            *(uint4*)aL = *(const uint4*)&Pl[ab];
            #pragma unroll
            for (int nj = 0; nj < 8; ++nj) {
                uint32_t bH[2], bL[2];
                const int bb = ((nj * 4 + ks) * 32 + lane) * 2;
                *(uint2*)bH = *(const uint2*)&Vh[bb];
                *(uint2*)bL = *(const uint2*)&Vl[bb];
                mma8(oacc[nj], aH, bH);
                mma8(oacc[nj], aH, bL);
                mma8(oacc[nj], aL, bH);
            }
        }
    }

    // ---- epilogue ----
    const float inv0 = 1.f / l0, inv1 = 1.f / l1;
    const int row = q0 + warp * 16 + (lane >> 2);
    #pragma unroll
    for (int nj = 0; nj < 8; ++nj) {
        const int col = h * DK_ + nj * 8 + 2 * (lane & 3);
        float2 v0 = {oacc[nj][0] * inv0, oacc[nj][1] * inv0};
        float2 v1 = {oacc[nj][2] * inv1, oacc[nj][3] * inv1};
        *(float2*)(att + ((size_t)b * L_ + row) * HD_ + col) = v0;
        *(float2*)(att + ((size_t)b * L_ + row + 8) * HD_ + col) = v1;
    }
}

// ---------------------------------------------------------------------------
// Launch
// ---------------------------------------------------------------------------
#define GEMM_SMEM  (16384 * 4)   // 64KB
#define ATTN_SMEM  (32768 * 4)   // 128KB

extern "C" void kernel_launch(void* const* d_in, const int* in_sizes, int n_in,
                              void* d_out, int out_size)
{
    const float* X    = (const float*)d_in[0];
    const float* Wqkv = (const float*)d_in[1];
    const float* bqkv = (const float*)d_in[2];
    const float* Wfc  = (const float*)d_in[3];
    const float* bfc  = (const float*)d_in[4];
    float* out = (float*)d_out;

    float *qkv = nullptr, *att = nullptr;
    cudaGetSymbolAddress((void**)&qkv, g_qkv);
    cudaGetSymbolAddress((void**)&att, g_att);

    cudaFuncSetAttribute(gemm_tf32x3,
                         cudaFuncAttributeMaxDynamicSharedMemorySize, GEMM_SMEM);
    cudaFuncSetAttribute(attn_tf32x3,
                         cudaFuncAttributeMaxDynamicSharedMemorySize, ATTN_SMEM);

    gemm_tf32x3<<<dim3(QKV_N / 128, MTOK / 128), 256, GEMM_SMEM>>>(
        X, Wqkv, bqkv, qkv, MTOK, QKV_N, E_);

    attn_tf32x3<<<dim3(L_ / 128, H_, B_), 256, ATTN_SMEM>>>(qkv, att);

    gemm_tf32x3<<<dim3(HD_ / 128, MTOK / 128), 256, GEMM_SMEM>>>(
        att, Wfc, bfc, out, MTOK, HD_, E_);
}

// round 5
// speedup vs baseline: 1.9240x; 1.9240x over previous
#include <cuda_runtime.h>
#include <cuda_bf16.h>
#include <math.h>
#include <stdint.h>

// Problem constants
#define B_    4
#define L_    2048
#define E_    1024
#define H_    16
#define DK_   64
#define MTOK  (B_ * L_)          // 8192
#define QKV_N (3 * H_ * DK_)     // 3072
#define HD_   (H_ * DK_)         // 1024
#define KDIM  1024

// ---------------------------------------------------------------------------
// Scratch (__device__ globals; allocation-free rule)
// ---------------------------------------------------------------------------
__device__ float         g_qkv[(size_t)MTOK * QKV_N];
__device__ float         g_att[(size_t)MTOK * HD_];
__device__ __nv_bfloat16 g_Xh[(size_t)MTOK * E_];
__device__ __nv_bfloat16 g_Xl[(size_t)MTOK * E_];
__device__ __nv_bfloat16 g_Wqh[(size_t)QKV_N * E_];   // transposed [N][K]
__device__ __nv_bfloat16 g_Wql[(size_t)QKV_N * E_];
__device__ __nv_bfloat16 g_Wfh[(size_t)E_ * HD_];     // transposed [N][K]
__device__ __nv_bfloat16 g_Wfl[(size_t)E_ * HD_];
__device__ __nv_bfloat16 g_Ath[(size_t)MTOK * HD_];
__device__ __nv_bfloat16 g_Atl[(size_t)MTOK * HD_];

// ---------------------------------------------------------------------------
// PTX helpers (sm_80+ features only: ldmatrix, mma.sync bf16, cp.async)
// ---------------------------------------------------------------------------
__device__ __forceinline__ uint32_t smem_u32(const void* p) {
    uint32_t a;
    asm("{ .reg .u64 t; cvta.to.shared.u64 t, %1; cvt.u32.u64 %0, t; }"
        : "=r"(a) : "l"(p));
    return a;
}
__device__ __forceinline__ void ldsm4(uint32_t* r, uint32_t addr) {
    asm volatile("ldmatrix.sync.aligned.m8n8.x4.shared.b16 {%0,%1,%2,%3}, [%4];"
        : "=r"(r[0]), "=r"(r[1]), "=r"(r[2]), "=r"(r[3]) : "r"(addr));
}
__device__ __forceinline__ void mma_bf16(float* c, const uint32_t* a, const uint32_t* b) {
    asm volatile(
        "mma.sync.aligned.m16n8k16.row.col.f32.bf16.bf16.f32 "
        "{%0,%1,%2,%3},{%4,%5,%6,%7},{%8,%9},{%0,%1,%2,%3};"
        : "+f"(c[0]), "+f"(c[1]), "+f"(c[2]), "+f"(c[3])
        : "r"(a[0]), "r"(a[1]), "r"(a[2]), "r"(a[3]), "r"(b[0]), "r"(b[1]));
}
__device__ __forceinline__ void cp16(uint32_t dst, const void* src) {
    asm volatile("cp.async.cg.shared.global [%0], [%1], 16;" :: "r"(dst), "l"(src));
}
#define CP_COMMIT() asm volatile("cp.async.commit_group;" ::: "memory")
#define CP_WAIT1()  asm volatile("cp.async.wait_group 1;" ::: "memory")
#define CP_WAIT0()  asm volatile("cp.async.wait_group 0;" ::: "memory")

// ---------------------------------------------------------------------------
// Conversion kernels (fp32 -> bf16 hi/lo)
// ---------------------------------------------------------------------------
__global__ void convert_split(const float4* __restrict__ in,
                              uint32_t* __restrict__ hi2, uint32_t* __restrict__ lo2,
                              int n4)
{
    int i = blockIdx.x * blockDim.x + threadIdx.x;
    if (i >= n4) return;
    float4 v = in[i];
    __nv_bfloat16 hx = __float2bfloat16_rn(v.x), hy = __float2bfloat16_rn(v.y);
    __nv_bfloat16 hz = __float2bfloat16_rn(v.z), hw = __float2bfloat16_rn(v.w);
    __nv_bfloat16 lx = __float2bfloat16_rn(v.x - __bfloat162float(hx));
    __nv_bfloat16 ly = __float2bfloat16_rn(v.y - __bfloat162float(hy));
    __nv_bfloat16 lz = __float2bfloat16_rn(v.z - __bfloat162float(hz));
    __nv_bfloat16 lw = __float2bfloat16_rn(v.w - __bfloat162float(hw));
    __nv_bfloat162 h01; h01.x = hx; h01.y = hy;
    __nv_bfloat162 h23; h23.x = hz; h23.y = hw;
    __nv_bfloat162 l01; l01.x = lx; l01.y = ly;
    __nv_bfloat162 l23; l23.x = lz; l23.y = lw;
    hi2[2 * i]     = *(uint32_t*)&h01;
    hi2[2 * i + 1] = *(uint32_t*)&h23;
    lo2[2 * i]     = *(uint32_t*)&l01;
    lo2[2 * i + 1] = *(uint32_t*)&l23;
}

// W[K][N] row-major -> T[N][K] bf16 hi/lo (transpose + split)
__global__ __launch_bounds__(256) void wt_convert(
    const float* __restrict__ W, __nv_bfloat16* __restrict__ Th,
    __nv_bfloat16* __restrict__ Tl, int K, int N)
{
    __shared__ float tile[32][33];
    const int n0 = blockIdx.x * 32, k0 = blockIdx.y * 32;
    const int tx = threadIdx.x & 31, ty = threadIdx.x >> 5;
    #pragma unroll
    for (int r = 0; r < 32; r += 8)
        tile[ty + r][tx] = W[(size_t)(k0 + ty + r) * N + n0 + tx];
    __syncthreads();
    #pragma unroll
    for (int r = 0; r < 32; r += 8) {
        const int n = n0 + ty + r, k = k0 + tx;
        const float x = tile[tx][ty + r];
        const __nv_bfloat16 h = __float2bfloat16_rn(x);
        Th[(size_t)n * K + k] = h;
        Tl[(size_t)n * K + k] = __float2bfloat16_rn(x - __bfloat162float(h));
    }
}

// ---------------------------------------------------------------------------
// bf16x3 GEMM: C[M,N] = A[M,K] @ Bt[N,K]^T + bias.
// Block tile 128x128, BK=32, 256 threads = 8 warps (2m x 4n), warp = 64x32.
// SMEM: per buffer 32KB = Ah(8K) Al(8K) Bh(8K) Bl(8K), double-buffered = 64KB.
// Layout: 8x8-b16 tiles stored contiguously (128B each): conflict-free LDSM.
//   tile(rt, kt) at offset (rt*4 + kt)*128; within tile row r: +r*16.
// ---------------------------------------------------------------------------
#define GEMM_SMEM_BYTES 65536
#define NCHUNK (KDIM / 32)   // 32

__global__ __launch_bounds__(256) void gemm_bf16x3(
    const __nv_bfloat16* __restrict__ Agh, const __nv_bfloat16* __restrict__ Agl,
    const __nv_bfloat16* __restrict__ Bgh, const __nv_bfloat16* __restrict__ Bgl,
    const float* __restrict__ bias, float* __restrict__ C, int N)
{
    extern __shared__ __align__(1024) char smem[];
    const uint32_t sbase = smem_u32(smem);
    const int tid = threadIdx.x, lane = tid & 31, warp = tid >> 5;
    const int wm = warp & 1, wn = warp >> 1;
    const int brow = blockIdx.y * 128, bcol = blockIdx.x * 128;

    float acc[4][4][4] = {};

    // ---- staging: 512 x 16B per operand-half; thread does idx = tid, tid+256
    auto stage = [&](int kt, int buf) {
        const int k0 = kt * 32;
        const uint32_t b0 = sbase + buf * 32768;
        #pragma unroll
        for (int p = 0; p < 2; ++p) {
            const int idx = tid + p * 256;
            const int r = idx & 127, kc = idx >> 7;   // kc = 0..3 (8 bf16 = 16B)
            const uint32_t soff = (uint32_t)(((r >> 3) * 4 + kc) * 128 + (r & 7) * 16);
            const size_t ga = (size_t)(brow + r) * KDIM + k0 + kc * 8;
            const size_t gb = (size_t)(bcol + r) * KDIM + k0 + kc * 8;
            cp16(b0 + soff,         Agh + ga);
            cp16(b0 + 8192 + soff,  Agl + ga);
            cp16(b0 + 16384 + soff, Bgh + gb);
            cp16(b0 + 24576 + soff, Bgl + gb);
        }
    };

    auto compute = [&](int buf) {
        const uint32_t b0 = sbase + buf * 32768;
        const int g = lane >> 3, row = lane & 7;
        #pragma unroll
        for (int s = 0; s < 2; ++s) {           // two k16 steps per chunk
            uint32_t aH[4][4], aL[4][4], bH[2][4], bL[2][4];
            #pragma unroll
            for (int mi = 0; mi < 4; ++mi) {
                // A mats: (mt0,ks0)(mt0+1,ks0)(mt0,ks1)(mt0+1,ks1)
                const int mt0 = wm * 8 + mi * 2;
                const uint32_t tile = (uint32_t)((mt0 + (g & 1)) * 4 + 2 * s + (g >> 1));
                const uint32_t addr = b0 + tile * 128 + row * 16;
                ldsm4(aH[mi], addr);
                ldsm4(aL[mi], addr + 8192);
            }
            #pragma unroll
            for (int hf = 0; hf < 2; ++hf) {
                // B mats: (ng,ks0)(ng,ks1)(ng+1,ks0)(ng+1,ks1)
                const int ng = wn * 4 + hf * 2;
                const uint32_t tile = (uint32_t)((ng + (g >> 1)) * 4 + 2 * s + (g & 1));
                const uint32_t addr = b0 + 16384 + tile * 128 + row * 16;
                ldsm4(bH[hf], addr);
                ldsm4(bL[hf], addr + 8192);
            }
            #pragma unroll
            for (int mi = 0; mi < 4; ++mi)
                #pragma unroll
                for (int nj = 0; nj < 4; ++nj) {
                    const uint32_t* bh = &bH[nj >> 1][(nj & 1) * 2];
                    const uint32_t* bl = &bL[nj >> 1][(nj & 1) * 2];
                    mma_bf16(acc[mi][nj], aH[mi], bh);   // hi*hi
                    mma_bf16(acc[mi][nj], aH[mi], bl);   // hi*lo
                    mma_bf16(acc[mi][nj], aL[mi], bh);   // lo*hi
                }
        }
    };

    stage(0, 0);
    CP_COMMIT();
    for (int kt = 0; kt < NCHUNK; ++kt) {
        if (kt + 1 < NCHUNK) {
            stage(kt + 1, (kt + 1) & 1);
            CP_COMMIT();
            CP_WAIT1();
        } else {
            CP_WAIT0();
        }
        __syncthreads();
        compute(kt & 1);
        __syncthreads();   // protect buffer from next stage() overwrite
    }

    // ---- epilogue: c-frag rows l/4 (+8), cols 2(l%4)
    const int r4 = lane >> 2, c2 = (lane & 3) * 2;
    #pragma unroll
    for (int mi = 0; mi < 4; ++mi) {
        const int row = brow + wm * 64 + mi * 16 + r4;
        #pragma unroll
        for (int nj = 0; nj < 4; ++nj) {
            const int col = bcol + wn * 32 + nj * 8 + c2;
            const float b0 = __ldg(&bias[col]), b1 = __ldg(&bias[col + 1]);
            float2 v0 = {acc[mi][nj][0] + b0, acc[mi][nj][1] + b1};
            float2 v1 = {acc[mi][nj][2] + b0, acc[mi][nj][3] + b1};
            *(float2*)(C + (size_t)row * N + col) = v0;
            *(float2*)(C + (size_t)(row + 8) * N + col) = v1;
        }
    }
}

// ---------------------------------------------------------------------------
// Flash-attention (fp32, online softmax) — round-1 kernel, unchanged.
// ---------------------------------------------------------------------------
#define ATT_PITCH 68
#define ATT_SMEM_BYTES (4 * 64 * ATT_PITCH * (int)sizeof(float))

__global__ __launch_bounds__(256) void attn_kernel(
    const float* __restrict__ qkv, float* __restrict__ att)
{
    extern __shared__ float sm[];
    float* Qt = sm;
    float* Kt = Qt + 64 * ATT_PITCH;
    float* Vs = Kt + 64 * ATT_PITCH;
    float* Pt = Vs + 64 * ATT_PITCH;

    const int b  = blockIdx.z;
    const int h  = blockIdx.y;
    const int q0 = blockIdx.x * 64;
    const int tid = threadIdx.x;
    const int ty = tid >> 4;
    const int tx = tid & 15;

    const size_t base = ((size_t)b * L_) * QKV_N + (size_t)h * (3 * DK_);

    for (int t = tid; t < 64 * 16; t += 256) {
        const int q  = t >> 4;
        const int d4 = (t & 15) << 2;
        float4 v = *(const float4*)(qkv + base + (size_t)(q0 + q) * QKV_N + d4);
        Qt[(d4 + 0) * ATT_PITCH + q] = v.x;
        Qt[(d4 + 1) * ATT_PITCH + q] = v.y;
        Qt[(d4 + 2) * ATT_PITCH + q] = v.z;
        Qt[(d4 + 3) * ATT_PITCH + q] = v.w;
    }

    float o[4][4];
    float m_i[4], l_i[4];
    #pragma unroll
    for (int i = 0; i < 4; ++i) {
        m_i[i] = -INFINITY; l_i[i] = 0.f;
        #pragma unroll
        for (int j = 0; j < 4; ++j) o[i][j] = 0.f;
    }
    const float scale = 0.125f;

    for (int kc = 0; kc < L_; kc += 64) {
        __syncthreads();
        for (int t = tid; t < 64 * 16; t += 256) {
            const int j  = t >> 4;
            const int d4 = (t & 15) << 2;
            const float* rp = qkv + base + (size_t)(kc + j) * QKV_N;
            float4 kv = *(const float4*)(rp + DK_ + d4);
            Kt[(d4 + 0) * ATT_PITCH + j] = kv.x;
            Kt[(d4 + 1) * ATT_PITCH + j] = kv.y;
            Kt[(d4 + 2) * ATT_PITCH + j] = kv.z;
            Kt[(d4 + 3) * ATT_PITCH + j] = kv.w;
            float4 vv = *(const float4*)(rp + 2 * DK_ + d4);
            *(float4*)&Vs[j * ATT_PITCH + d4] = vv;
        }
        __syncthreads();

        float s[4][4];
        #pragma unroll
        for (int i = 0; i < 4; ++i)
            #pragma unroll
            for (int j = 0; j < 4; ++j) s[i][j] = 0.f;

        #pragma unroll 4
        for (int d = 0; d < 64; ++d) {
            const float4 qa = *(const float4*)(Qt + d * ATT_PITCH + ty * 4);
            const float4 kb = *(const float4*)(Kt + d * ATT_PITCH + tx * 4);
            const float qv[4] = {qa.x, qa.y, qa.z, qa.w};
            const float kv[4] = {kb.x, kb.y, kb.z, kb.w};
            #pragma unroll
            for (int i = 0; i < 4; ++i)
                #pragma unroll
                for (int j = 0; j < 4; ++j)
                    s[i][j] = fmaf(qv[i], kv[j], s[i][j]);
        }

        #pragma unroll
        for (int i = 0; i < 4; ++i) {
            float mloc = -INFINITY;
            #pragma unroll
            for (int j = 0; j < 4; ++j) {
                s[i][j] *= scale;
                mloc = fmaxf(mloc, s[i][j]);
            }
            #pragma unroll
            for (int off = 8; off > 0; off >>= 1)
                mloc = fmaxf(mloc, __shfl_xor_sync(0xffffffffu, mloc, off, 16));

            const float mnew = fmaxf(m_i[i], mloc);
            const float corr = __expf(m_i[i] - mnew);
            m_i[i] = mnew;

            float lsum = 0.f;
            #pragma unroll
            for (int j = 0; j < 4; ++j) {
                const float p = __expf(s[i][j] - mnew);
                s[i][j] = p;
                lsum += p;
            }
            #pragma unroll
            for (int off = 8; off > 0; off >>= 1)
                lsum += __shfl_xor_sync(0xffffffffu, lsum, off, 16);

            l_i[i] = l_i[i] * corr + lsum;
            #pragma unroll
            for (int j = 0; j < 4; ++j) o[i][j] *= corr;
        }

        #pragma unroll
        for (int j = 0; j < 4; ++j)
            #pragma unroll
            for (int i = 0; i < 4; ++i)
                Pt[(tx * 4 + j) * ATT_PITCH + ty * 4 + i] = s[i][j];
        __syncthreads();

        #pragma unroll 4
        for (int j = 0; j < 64; ++j) {
            const float4 pa = *(const float4*)(Pt + j * ATT_PITCH + ty * 4);
            const float4 vb = *(const float4*)(Vs + j * ATT_PITCH + tx * 4);
            const float pv[4] = {pa.x, pa.y, pa.z, pa.w};
            const float vv[4] = {vb.x, vb.y, vb.z, vb.w};
            #pragma unroll
            for (int i = 0; i < 4; ++i)
                #pragma unroll
                for (int d = 0; d < 4; ++d)
                    o[i][d] = fmaf(pv[i], vv[d], o[i][d]);
        }
    }

    #pragma unroll
    for (int i = 0; i < 4; ++i) {
        const float inv = 1.f / l_i[i];
        float4 v;
        v.x = o[i][0] * inv; v.y = o[i][1] * inv;
        v.z = o[i][2] * inv; v.w = o[i][3] * inv;
        const size_t idx = ((size_t)b * L_ + q0 + ty * 4 + i) * HD_
                         + (size_t)h * DK_ + tx * 4;
        *(float4*)(att + idx) = v;
    }
}

// ---------------------------------------------------------------------------
// Launch
// ---------------------------------------------------------------------------
extern "C" void kernel_launch(void* const* d_in, const int* in_sizes, int n_in,
                              void* d_out, int out_size)
{
    const float* X    = (const float*)d_in[0];
    const float* Wqkv = (const float*)d_in[1];
    const float* bqkv = (const float*)d_in[2];
    const float* Wfc  = (const float*)d_in[3];
    const float* bfc  = (const float*)d_in[4];
    float* out = (float*)d_out;

    float *qkv, *att;
    __nv_bfloat16 *Xh, *Xl, *Wqh, *Wql, *Wfh, *Wfl, *Ath, *Atl;
    cudaGetSymbolAddress((void**)&qkv, g_qkv);
    cudaGetSymbolAddress((void**)&att, g_att);
    cudaGetSymbolAddress((void**)&Xh, g_Xh);
    cudaGetSymbolAddress((void**)&Xl, g_Xl);
    cudaGetSymbolAddress((void**)&Wqh, g_Wqh);
    cudaGetSymbolAddress((void**)&Wql, g_Wql);
    cudaGetSymbolAddress((void**)&Wfh, g_Wfh);
    cudaGetSymbolAddress((void**)&Wfl, g_Wfl);
    cudaGetSymbolAddress((void**)&Ath, g_Ath);
    cudaGetSymbolAddress((void**)&Atl, g_Atl);

    cudaFuncSetAttribute(gemm_bf16x3,
                         cudaFuncAttributeMaxDynamicSharedMemorySize, GEMM_SMEM_BYTES);
    cudaFuncSetAttribute(attn_kernel,
                         cudaFuncAttributeMaxDynamicSharedMemorySize, ATT_SMEM_BYTES);

    // 0) conversions
    {
        const int n4 = MTOK * E_ / 4;
        convert_split<<<(n4 + 255) / 256, 256>>>(
            (const float4*)X, (uint32_t*)Xh, (uint32_t*)Xl, n4);
        wt_convert<<<dim3(QKV_N / 32, KDIM / 32), 256>>>(Wqkv, Wqh, Wql, KDIM, QKV_N);
        wt_convert<<<dim3(HD_ / 32, KDIM / 32), 256>>>(Wfc, Wfh, Wfl, KDIM, HD_);
    }

    // 1) QKV = X @ Wqkv + b
    gemm_bf16x3<<<dim3(QKV_N / 128, MTOK / 128), 256, GEMM_SMEM_BYTES>>>(
        Xh, Xl, Wqh, Wql, bqkv, qkv, QKV_N);

    // 2) attention
    attn_kernel<<<dim3(L_ / 64, H_, B_), 256, ATT_SMEM_BYTES>>>(qkv, att);

    // 3) FC
    {
        const int n4 = MTOK * HD_ / 4;
        convert_split<<<(n4 + 255) / 256, 256>>>(
            (const float4*)att, (uint32_t*)Ath, (uint32_t*)Atl, n4);
    }
    gemm_bf16x3<<<dim3(HD_ / 128, MTOK / 128), 256, GEMM_SMEM_BYTES>>>(
        Ath, Atl, Wfh, Wfl, bfc, out, HD_);
}

// round 6
// speedup vs baseline: 3.0421x; 1.5811x over previous
#include <cuda_runtime.h>
#include <cuda_bf16.h>
#include <math.h>
#include <stdint.h>

// Problem constants
#define B_    4
#define L_    2048
#define E_    1024
#define H_    16
#define DK_   64
#define MTOK  (B_ * L_)          // 8192
#define QKV_N (3 * H_ * DK_)     // 3072
#define HD_   (H_ * DK_)         // 1024
#define KDIM  1024

// ---------------------------------------------------------------------------
// Scratch (__device__ globals; allocation-free rule)
// ---------------------------------------------------------------------------
__device__ __nv_bfloat16 g_Xh[(size_t)MTOK * E_];
__device__ __nv_bfloat16 g_Xl[(size_t)MTOK * E_];
__device__ __nv_bfloat16 g_Wqh[(size_t)QKV_N * E_];     // transposed [N][K]
__device__ __nv_bfloat16 g_Wql[(size_t)QKV_N * E_];
__device__ __nv_bfloat16 g_Wfh[(size_t)E_ * HD_];       // transposed [N][K]
__device__ __nv_bfloat16 g_Wfl[(size_t)E_ * HD_];
__device__ __nv_bfloat16 g_qkvh[(size_t)MTOK * QKV_N];  // [token][3*H*DK]
__device__ __nv_bfloat16 g_qkvl[(size_t)MTOK * QKV_N];
__device__ __nv_bfloat16 g_Ath[(size_t)MTOK * HD_];     // attention out hi/lo
__device__ __nv_bfloat16 g_Atl[(size_t)MTOK * HD_];

// ---------------------------------------------------------------------------
// PTX helpers (sm_80+ only: ldmatrix, mma.sync bf16, cp.async)
// ---------------------------------------------------------------------------
__device__ __forceinline__ uint32_t smem_u32(const void* p) {
    uint32_t a;
    asm("{ .reg .u64 t; cvta.to.shared.u64 t, %1; cvt.u32.u64 %0, t; }"
        : "=r"(a) : "l"(p));
    return a;
}
__device__ __forceinline__ void ldsm4(uint32_t* r, uint32_t addr) {
    asm volatile("ldmatrix.sync.aligned.m8n8.x4.shared.b16 {%0,%1,%2,%3}, [%4];"
        : "=r"(r[0]), "=r"(r[1]), "=r"(r[2]), "=r"(r[3]) : "r"(addr));
}
__device__ __forceinline__ void ldsm4t(uint32_t* r, uint32_t addr) {
    asm volatile("ldmatrix.sync.aligned.m8n8.x4.trans.shared.b16 {%0,%1,%2,%3}, [%4];"
        : "=r"(r[0]), "=r"(r[1]), "=r"(r[2]), "=r"(r[3]) : "r"(addr));
}
__device__ __forceinline__ void mma_bf16(float* c, const uint32_t* a, const uint32_t* b) {
    asm volatile(
        "mma.sync.aligned.m16n8k16.row.col.f32.bf16.bf16.f32 "
        "{%0,%1,%2,%3},{%4,%5,%6,%7},{%8,%9},{%0,%1,%2,%3};"
        : "+f"(c[0]), "+f"(c[1]), "+f"(c[2]), "+f"(c[3])
        : "r"(a[0]), "r"(a[1]), "r"(a[2]), "r"(a[3]), "r"(b[0]), "r"(b[1]));
}
__device__ __forceinline__ void cp16(uint32_t dst, const void* src) {
    asm volatile("cp.async.cg.shared.global [%0], [%1], 16;" :: "r"(dst), "l"(src));
}
#define CP_COMMIT() asm volatile("cp.async.commit_group;" ::: "memory")
#define CP_WAIT1()  asm volatile("cp.async.wait_group 1;" ::: "memory")
#define CP_WAIT0()  asm volatile("cp.async.wait_group 0;" ::: "memory")

__device__ __forceinline__ uint32_t pack_hi(float x, float y, uint32_t& lo) {
    __nv_bfloat162 h, l;
    h.x = __float2bfloat16_rn(x);
    h.y = __float2bfloat16_rn(y);
    l.x = __float2bfloat16_rn(x - __bfloat162float(h.x));
    l.y = __float2bfloat16_rn(y - __bfloat162float(h.y));
    lo = *(uint32_t*)&l;
    return *(uint32_t*)&h;
}

// ---------------------------------------------------------------------------
// Conversion kernels (fp32 -> bf16 hi/lo)
// ---------------------------------------------------------------------------
__global__ void convert_split(const float4* __restrict__ in,
                              uint32_t* __restrict__ hi2, uint32_t* __restrict__ lo2,
                              int n4)
{
    int i = blockIdx.x * blockDim.x + threadIdx.x;
    if (i >= n4) return;
    float4 v = in[i];
    uint32_t l0, l1;
    uint32_t h0 = pack_hi(v.x, v.y, l0);
    uint32_t h1 = pack_hi(v.z, v.w, l1);
    hi2[2 * i] = h0; hi2[2 * i + 1] = h1;
    lo2[2 * i] = l0; lo2[2 * i + 1] = l1;
}

// W[K][N] row-major -> T[N][K] bf16 hi/lo (transpose + split)
__global__ __launch_bounds__(256) void wt_convert(
    const float* __restrict__ W, __nv_bfloat16* __restrict__ Th,
    __nv_bfloat16* __restrict__ Tl, int K, int N)
{
    __shared__ float tile[32][33];
    const int n0 = blockIdx.x * 32, k0 = blockIdx.y * 32;
    const int tx = threadIdx.x & 31, ty = threadIdx.x >> 5;
    #pragma unroll
    for (int r = 0; r < 32; r += 8)
        tile[ty + r][tx] = W[(size_t)(k0 + ty + r) * N + n0 + tx];
    __syncthreads();
    #pragma unroll
    for (int r = 0; r < 32; r += 8) {
        const int n = n0 + ty + r, k = k0 + tx;
        const float x = tile[tx][ty + r];
        const __nv_bfloat16 h = __float2bfloat16_rn(x);
        Th[(size_t)n * K + k] = h;
        Tl[(size_t)n * K + k] = __float2bfloat16_rn(x - __bfloat162float(h));
    }
}

// ---------------------------------------------------------------------------
// bf16x3 GEMM: 128x128 tile, BK=32, 256 thr = 8 warps (2m x 4n), warp 64x32.
// SMEM 2 x 32KB double buffer; 8x8-b16 tiles contiguous (128B) for LDSM.
// Epilogue: fp32 (Cf) or bf16 hi/lo (Cbh/Cbl), selected by null-ness.
// ---------------------------------------------------------------------------
#define GEMM_SMEM_BYTES 65536
#define NCHUNK (KDIM / 32)

__global__ __launch_bounds__(256) void gemm_bf16x3(
    const __nv_bfloat16* __restrict__ Agh, const __nv_bfloat16* __restrict__ Agl,
    const __nv_bfloat16* __restrict__ Bgh, const __nv_bfloat16* __restrict__ Bgl,
    const float* __restrict__ bias, float* __restrict__ Cf,
    __nv_bfloat16* __restrict__ Cbh, __nv_bfloat16* __restrict__ Cbl, int N)
{
    extern __shared__ __align__(1024) char smem[];
    const uint32_t sbase = smem_u32(smem);
    const int tid = threadIdx.x, lane = tid & 31, warp = tid >> 5;
    const int wm = warp & 1, wn = warp >> 1;
    const int brow = blockIdx.y * 128, bcol = blockIdx.x * 128;

    float acc[4][4][4] = {};

    auto stage = [&](int kt, int buf) {
        const int k0 = kt * 32;
        const uint32_t b0 = sbase + buf * 32768;
        #pragma unroll
        for (int p = 0; p < 2; ++p) {
            const int idx = tid + p * 256;
            const int r = idx & 127, kc = idx >> 7;
            const uint32_t soff = (uint32_t)(((r >> 3) * 4 + kc) * 128 + (r & 7) * 16);
            const size_t ga = (size_t)(brow + r) * KDIM + k0 + kc * 8;
            const size_t gb = (size_t)(bcol + r) * KDIM + k0 + kc * 8;
            cp16(b0 + soff,         Agh + ga);
            cp16(b0 + 8192 + soff,  Agl + ga);
            cp16(b0 + 16384 + soff, Bgh + gb);
            cp16(b0 + 24576 + soff, Bgl + gb);
        }
    };

    auto compute = [&](int buf) {
        const uint32_t b0 = sbase + buf * 32768;
        const int g = lane >> 3, row = lane & 7;
        #pragma unroll
        for (int s = 0; s < 2; ++s) {
            uint32_t aH[4][4], aL[4][4], bH[2][4], bL[2][4];
            #pragma unroll
            for (int mi = 0; mi < 4; ++mi) {
                const int mt0 = wm * 8 + mi * 2;
                const uint32_t tile = (uint32_t)((mt0 + (g & 1)) * 4 + 2 * s + (g >> 1));
                const uint32_t addr = b0 + tile * 128 + row * 16;
                ldsm4(aH[mi], addr);
                ldsm4(aL[mi], addr + 8192);
            }
            #pragma unroll
            for (int hf = 0; hf < 2; ++hf) {
                const int ng = wn * 4 + hf * 2;
                const uint32_t tile = (uint32_t)((ng + (g >> 1)) * 4 + 2 * s + (g & 1));
                const uint32_t addr = b0 + 16384 + tile * 128 + row * 16;
                ldsm4(bH[hf], addr);
                ldsm4(bL[hf], addr + 8192);
            }
            #pragma unroll
            for (int mi = 0; mi < 4; ++mi)
                #pragma unroll
                for (int nj = 0; nj < 4; ++nj) {
                    const uint32_t* bh = &bH[nj >> 1][(nj & 1) * 2];
                    const uint32_t* bl = &bL[nj >> 1][(nj & 1) * 2];
                    mma_bf16(acc[mi][nj], aH[mi], bh);
                    mma_bf16(acc[mi][nj], aH[mi], bl);
                    mma_bf16(acc[mi][nj], aL[mi], bh);
                }
        }
    };

    stage(0, 0);
    CP_COMMIT();
    for (int kt = 0; kt < NCHUNK; ++kt) {
        if (kt + 1 < NCHUNK) {
            stage(kt + 1, (kt + 1) & 1);
            CP_COMMIT();
            CP_WAIT1();
        } else {
            CP_WAIT0();
        }
        __syncthreads();
        compute(kt & 1);
        __syncthreads();
    }

    const int r4 = lane >> 2, c2 = (lane & 3) * 2;
    #pragma unroll
    for (int mi = 0; mi < 4; ++mi) {
        const int row = brow + wm * 64 + mi * 16 + r4;
        #pragma unroll
        for (int nj = 0; nj < 4; ++nj) {
            const int col = bcol + wn * 32 + nj * 8 + c2;
            const float b0 = __ldg(&bias[col]), b1 = __ldg(&bias[col + 1]);
            const float x0 = acc[mi][nj][0] + b0, y0 = acc[mi][nj][1] + b1;
            const float x1 = acc[mi][nj][2] + b0, y1 = acc[mi][nj][3] + b1;
            if (Cf) {
                *(float2*)(Cf + (size_t)row * N + col) = make_float2(x0, y0);
                *(float2*)(Cf + (size_t)(row + 8) * N + col) = make_float2(x1, y1);
            } else {
                uint32_t l0, l1;
                const uint32_t h0 = pack_hi(x0, y0, l0);
                const uint32_t h1 = pack_hi(x1, y1, l1);
                *(uint32_t*)(Cbh + (size_t)row * N + col) = h0;
                *(uint32_t*)(Cbl + (size_t)row * N + col) = l0;
                *(uint32_t*)(Cbh + (size_t)(row + 8) * N + col) = h1;
                *(uint32_t*)(Cbl + (size_t)(row + 8) * N + col) = l1;
            }
        }
    }
}

// ---------------------------------------------------------------------------
// Flash attention, bf16x3 mma. Grid (L/128, H, B), 256 thr = 8 warps.
// Warp w owns q rows [16w, 16w+16). Key chunks of 64.
// SMEM (96KB): QH 0(16K) QL 16K | KH 32K(8K) KL 40K | VH 48K(8K) VL 56K
//              PH 64K(16K = 8 warps x 2K) PL 80K
// Tile layouts (8x8-b16 tiles, 128B each, row-of-8 k-tiles):
//   Q: tile(rt,kt)= (rt*8+kt), rt=q>>3 (0..15), kt=d>>3 (0..7)
//   K: rt=key>>3 (0..7), kt=d>>3
//   V: tile(kt_key, dt) = kt_key*8+dt  (rows=key)
//   P (per warp, 2KB): tile(rt,kt)= rt*8+kt, rt=q16>>3 (0..1), kt=key>>3 (0..7)
// ---------------------------------------------------------------------------
#define AS_QH 0
#define AS_QL 16384
#define AS_KH 32768
#define AS_KL 40960
#define AS_VH 49152
#define AS_VL 57344
#define AS_PH 65536
#define AS_PL 81920
#define ATTN_SMEM_BYTES 98304

__global__ __launch_bounds__(256) void attn_bf16x3(
    const __nv_bfloat16* __restrict__ qh, const __nv_bfloat16* __restrict__ ql,
    __nv_bfloat16* __restrict__ oh, __nv_bfloat16* __restrict__ ol)
{
    extern __shared__ __align__(1024) char smem[];
    const uint32_t sbase = smem_u32(smem);
    const int b = blockIdx.z, h = blockIdx.y, q0 = blockIdx.x * 128;
    const int tid = threadIdx.x, lane = tid & 31, warp = tid >> 5;
    const int g = lane >> 3, lrow = lane & 7;
    const size_t hbase = (size_t)h * (3 * DK_);

    // ---- stage Q (128 x 64 hi/lo), 1024 16B chunks -> 4 per thread ----
    for (int idx = tid; idx < 1024; idx += 256) {
        const int r = idx >> 3, c = idx & 7;
        const uint32_t soff = (uint32_t)(((r >> 3) * 8 + c) * 128 + (r & 7) * 16);
        const size_t ga = ((size_t)b * L_ + q0 + r) * QKV_N + hbase + c * 8;
        cp16(sbase + AS_QH + soff, qh + ga);
        cp16(sbase + AS_QL + soff, ql + ga);
    }
    CP_COMMIT();

    float oacc[8][4] = {};
    float m0 = -INFINITY, m1 = -INFINITY, l0 = 0.f, l1 = 0.f;
    const float scale = 0.125f;
    const uint32_t pw = sbase + warp * 2048;   // per-warp P region offset base

    for (int kc = 0; kc < L_; kc += 64) {
        __syncthreads();   // all warps done reading prev K/V
        // ---- stage K,V chunk (64 x 64 each, hi/lo): 512 chunks -> 2/thread
        for (int idx = tid; idx < 512; idx += 256) {
            const int r = idx >> 3, c = idx & 7;
            const uint32_t soff = (uint32_t)(((r >> 3) * 8 + c) * 128 + (r & 7) * 16);
            const size_t ga = ((size_t)b * L_ + kc + r) * QKV_N + hbase + c * 8;
            cp16(sbase + AS_KH + soff, qh + ga + DK_);
            cp16(sbase + AS_KL + soff, ql + ga + DK_);
            cp16(sbase + AS_VH + soff, qh + ga + 2 * DK_);
            cp16(sbase + AS_VL + soff, ql + ga + 2 * DK_);
        }
        CP_COMMIT();
        CP_WAIT0();
        __syncthreads();

        // ---- S = Q K^T : 16(q) x 64(key), k = 64(d) ----
        float sacc[8][4] = {};
        #pragma unroll
        for (int s = 0; s < 4; ++s) {
            uint32_t aH[4], aL[4];
            {
                const int mt0 = warp * 2;
                const uint32_t tile = (uint32_t)((mt0 + (g & 1)) * 8 + 2 * s + (g >> 1));
                const uint32_t addr = sbase + AS_QH + tile * 128 + lrow * 16;
                ldsm4(aH, addr);
                ldsm4(aL, addr + (AS_QL - AS_QH));
            }
            #pragma unroll
            for (int hf = 0; hf < 4; ++hf) {
                uint32_t bH[4], bL[4];
                const int ng = hf * 2;
                const uint32_t tile = (uint32_t)((ng + (g >> 1)) * 8 + 2 * s + (g & 1));
                const uint32_t addr = sbase + AS_KH + tile * 128 + lrow * 16;
                ldsm4(bH, addr);
                ldsm4(bL, addr + (AS_KL - AS_KH));
                #pragma unroll
                for (int q = 0; q < 2; ++q) {
                    float* c = sacc[ng + q];
                    mma_bf16(c, aH, &bH[q * 2]);
                    mma_bf16(c, aH, &bL[q * 2]);
                    mma_bf16(c, aL, &bH[q * 2]);
                }
            }
        }

        // ---- online softmax (row0 = regs 0,1 ; row1 = regs 2,3) ----
        {
            float mloc = -INFINITY;
            #pragma unroll
            for (int nj = 0; nj < 8; ++nj) {
                sacc[nj][0] *= scale; sacc[nj][1] *= scale;
                mloc = fmaxf(mloc, fmaxf(sacc[nj][0], sacc[nj][1]));
            }
            mloc = fmaxf(mloc, __shfl_xor_sync(0xffffffffu, mloc, 1));
            mloc = fmaxf(mloc, __shfl_xor_sync(0xffffffffu, mloc, 2));
            const float mnew = fmaxf(m0, mloc);
            const float corr = __expf(m0 - mnew);
            m0 = mnew;
            float lsum = 0.f;
            #pragma unroll
            for (int nj = 0; nj < 8; ++nj) {
                const float p0 = __expf(sacc[nj][0] - mnew);
                const float p1 = __expf(sacc[nj][1] - mnew);
                sacc[nj][0] = p0; sacc[nj][1] = p1;
                lsum += p0 + p1;
            }
            lsum += __shfl_xor_sync(0xffffffffu, lsum, 1);
            lsum += __shfl_xor_sync(0xffffffffu, lsum, 2);
            l0 = l0 * corr + lsum;
            #pragma unroll
            for (int nj = 0; nj < 8; ++nj) { oacc[nj][0] *= corr; oacc[nj][1] *= corr; }
        }
        {
            float mloc = -INFINITY;
            #pragma unroll
            for (int nj = 0; nj < 8; ++nj) {
                sacc[nj][2] *= scale; sacc[nj][3] *= scale;
                mloc = fmaxf(mloc, fmaxf(sacc[nj][2], sacc[nj][3]));
            }
            mloc = fmaxf(mloc, __shfl_xor_sync(0xffffffffu, mloc, 1));
            mloc = fmaxf(mloc, __shfl_xor_sync(0xffffffffu, mloc, 2));
            const float mnew = fmaxf(m1, mloc);
            const float corr = __expf(m1 - mnew);
            m1 = mnew;
            float lsum = 0.f;
            #pragma unroll
            for (int nj = 0; nj < 8; ++nj) {
                const float p0 = __expf(sacc[nj][2] - mnew);
                const float p1 = __expf(sacc[nj][3] - mnew);
                sacc[nj][2] = p0; sacc[nj][3] = p1;
                lsum += p0 + p1;
            }
            lsum += __shfl_xor_sync(0xffffffffu, lsum, 1);
            lsum += __shfl_xor_sync(0xffffffffu, lsum, 2);
            l1 = l1 * corr + lsum;
            #pragma unroll
            for (int nj = 0; nj < 8; ++nj) { oacc[nj][2] *= corr; oacc[nj][3] *= corr; }
        }

        // ---- store P (16 x 64) hi/lo into per-warp tile region ----
        {
            const int r4 = lane >> 2, cb = 4 * (lane & 3);   // byte offset of col pair
            #pragma unroll
            for (int nj = 0; nj < 8; ++nj) {
                uint32_t plo;
                const uint32_t ph0 = pack_hi(sacc[nj][0], sacc[nj][1], plo);
                const uint32_t off0 = (uint32_t)((0 * 8 + nj) * 128 + r4 * 16 + cb);
                *(uint32_t*)(smem + AS_PH + warp * 2048 + off0) = ph0;
                *(uint32_t*)(smem + AS_PL + warp * 2048 + off0) = plo;
                const uint32_t ph1 = pack_hi(sacc[nj][2], sacc[nj][3], plo);
                const uint32_t off1 = (uint32_t)((1 * 8 + nj) * 128 + r4 * 16 + cb);
                *(uint32_t*)(smem + AS_PH + warp * 2048 + off1) = ph1;
                *(uint32_t*)(smem + AS_PL + warp * 2048 + off1) = plo;
            }
        }
        __syncwarp();

        // ---- O += P V : 16(q) x 64(d), k = 64(key) ----
        #pragma unroll
        for (int s = 0; s < 4; ++s) {
            uint32_t aH[4], aL[4];
            {
                const uint32_t tile = (uint32_t)((g & 1) * 8 + 2 * s + (g >> 1));
                const uint32_t addr = sbase + AS_PH + warp * 2048 + tile * 128 + lrow * 16;
                ldsm4(aH, addr);
                ldsm4(aL, addr + (AS_PL - AS_PH));
            }
            #pragma unroll
            for (int hf = 0; hf < 4; ++hf) {
                uint32_t bH[4], bL[4];
                const int dt = hf * 2;
                // V[key][d] row-major: trans-ldmatrix -> B fragments (n=d, k=key)
                const uint32_t tile = (uint32_t)((2 * s + (g & 1)) * 8 + dt + (g >> 1));
                const uint32_t addr = sbase + AS_VH + tile * 128 + lrow * 16;
                ldsm4t(bH, addr);
                ldsm4t(bL, addr + (AS_VL - AS_VH));
                #pragma unroll
                for (int q = 0; q < 2; ++q) {
                    float* c = oacc[dt + q];
                    mma_bf16(c, aH, &bH[q * 2]);
                    mma_bf16(c, aH, &bL[q * 2]);
                    mma_bf16(c, aL, &bH[q * 2]);
                }
            }
        }
    }

    // ---- epilogue: normalize, split, write bf16 hi/lo [token][HD] ----
    const float inv0 = 1.f / l0, inv1 = 1.f / l1;
    const int r4 = lane >> 2, c2 = 2 * (lane & 3);
    const size_t row0 = (size_t)b * L_ + q0 + warp * 16 + r4;
    #pragma unroll
    for (int nj = 0; nj < 8; ++nj) {
        const int col = h * DK_ + nj * 8 + c2;
        uint32_t lo;
        const uint32_t h0 = pack_hi(oacc[nj][0] * inv0, oacc[nj][1] * inv0, lo);
        *(uint32_t*)(oh + row0 * HD_ + col) = h0;
        *(uint32_t*)(ol + row0 * HD_ + col) = lo;
        const uint32_t h1 = pack_hi(oacc[nj][2] * inv1, oacc[nj][3] * inv1, lo);
        *(uint32_t*)(oh + (row0 + 8) * HD_ + col) = h1;
        *(uint32_t*)(ol + (row0 + 8) * HD_ + col) = lo;
    }
}

// ---------------------------------------------------------------------------
// Launch
// ---------------------------------------------------------------------------
extern "C" void kernel_launch(void* const* d_in, const int* in_sizes, int n_in,
                              void* d_out, int out_size)
{
    const float* X    = (const float*)d_in[0];
    const float* Wqkv = (const float*)d_in[1];
    const float* bqkv = (const float*)d_in[2];
    const float* Wfc  = (const float*)d_in[3];
    const float* bfc  = (const float*)d_in[4];
    float* out = (float*)d_out;

    __nv_bfloat16 *Xh, *Xl, *Wqh, *Wql, *Wfh, *Wfl, *qkvh, *qkvl, *Ath, *Atl;
    cudaGetSymbolAddress((void**)&Xh, g_Xh);
    cudaGetSymbolAddress((void**)&Xl, g_Xl);
    cudaGetSymbolAddress((void**)&Wqh, g_Wqh);
    cudaGetSymbolAddress((void**)&Wql, g_Wql);
    cudaGetSymbolAddress((void**)&Wfh, g_Wfh);
    cudaGetSymbolAddress((void**)&Wfl, g_Wfl);
    cudaGetSymbolAddress((void**)&qkvh, g_qkvh);
    cudaGetSymbolAddress((void**)&qkvl, g_qkvl);
    cudaGetSymbolAddress((void**)&Ath, g_Ath);
    cudaGetSymbolAddress((void**)&Atl, g_Atl);

    cudaFuncSetAttribute(gemm_bf16x3,
                         cudaFuncAttributeMaxDynamicSharedMemorySize, GEMM_SMEM_BYTES);
    cudaFuncSetAttribute(attn_bf16x3,
                         cudaFuncAttributeMaxDynamicSharedMemorySize, ATTN_SMEM_BYTES);

    // 0) conversions
    {
        const int n4 = MTOK * E_ / 4;
        convert_split<<<(n4 + 255) / 256, 256>>>(
            (const float4*)X, (uint32_t*)Xh, (uint32_t*)Xl, n4);
        wt_convert<<<dim3(QKV_N / 32, KDIM / 32), 256>>>(Wqkv, Wqh, Wql, KDIM, QKV_N);
        wt_convert<<<dim3(HD_ / 32, KDIM / 32), 256>>>(Wfc, Wfh, Wfl, KDIM, HD_);
    }

    // 1) QKV = X @ Wqkv + b -> bf16 hi/lo
    gemm_bf16x3<<<dim3(QKV_N / 128, MTOK / 128), 256, GEMM_SMEM_BYTES>>>(
        Xh, Xl, Wqh, Wql, bqkv, nullptr, qkvh, qkvl, QKV_N);

    // 2) attention -> bf16 hi/lo
    attn_bf16x3<<<dim3(L_ / 128, H_, B_), 256, ATTN_SMEM_BYTES>>>(
        qkvh, qkvl, Ath, Atl);

    // 3) FC -> fp32 out
    gemm_bf16x3<<<dim3(HD_ / 128, MTOK / 128), 256, GEMM_SMEM_BYTES>>>(
        Ath, Atl, Wfh, Wfl, bfc, out, nullptr, nullptr, HD_);
}

// round 7
// speedup vs baseline: 4.2059x; 1.3826x over previous
#include <cuda_runtime.h>
#include <cuda_fp16.h>
#include <math.h>
#include <stdint.h>

// Problem constants
#define B_    4
#define L_    2048
#define E_    1024
#define H_    16
#define DK_   64
#define MTOK  (B_ * L_)          // 8192
#define QKV_N (3 * H_ * DK_)     // 3072
#define HD_   (H_ * DK_)         // 1024
#define KDIM  1024

// ---------------------------------------------------------------------------
// Scratch (__device__ globals; allocation-free rule)
// ---------------------------------------------------------------------------
__device__ __half g_Xh[(size_t)MTOK * E_];
__device__ __half g_Xl[(size_t)MTOK * E_];
__device__ __half g_Wqh[(size_t)QKV_N * E_];     // transposed [N][K], hi only
__device__ __half g_Wfh[(size_t)E_ * HD_];       // transposed [N][K], hi only
__device__ __half g_qkvh[(size_t)MTOK * QKV_N];  // [token][3*H*DK]
__device__ __half g_qkvl[(size_t)MTOK * QKV_N];
__device__ __half g_Ath[(size_t)MTOK * HD_];     // attention out hi/lo
__device__ __half g_Atl[(size_t)MTOK * HD_];

// ---------------------------------------------------------------------------
// PTX helpers (sm_80+ only: ldmatrix, mma.sync f16, cp.async)
// ---------------------------------------------------------------------------
__device__ __forceinline__ uint32_t smem_u32(const void* p) {
    uint32_t a;
    asm("{ .reg .u64 t; cvta.to.shared.u64 t, %1; cvt.u32.u64 %0, t; }"
        : "=r"(a) : "l"(p));
    return a;
}
__device__ __forceinline__ void ldsm4(uint32_t* r, uint32_t addr) {
    asm volatile("ldmatrix.sync.aligned.m8n8.x4.shared.b16 {%0,%1,%2,%3}, [%4];"
        : "=r"(r[0]), "=r"(r[1]), "=r"(r[2]), "=r"(r[3]) : "r"(addr));
}
__device__ __forceinline__ void ldsm4t(uint32_t* r, uint32_t addr) {
    asm volatile("ldmatrix.sync.aligned.m8n8.x4.trans.shared.b16 {%0,%1,%2,%3}, [%4];"
        : "=r"(r[0]), "=r"(r[1]), "=r"(r[2]), "=r"(r[3]) : "r"(addr));
}
__device__ __forceinline__ void mma_f16(float* c, const uint32_t* a, const uint32_t* b) {
    asm volatile(
        "mma.sync.aligned.m16n8k16.row.col.f32.f16.f16.f32 "
        "{%0,%1,%2,%3},{%4,%5,%6,%7},{%8,%9},{%0,%1,%2,%3};"
        : "+f"(c[0]), "+f"(c[1]), "+f"(c[2]), "+f"(c[3])
        : "r"(a[0]), "r"(a[1]), "r"(a[2]), "r"(a[3]), "r"(b[0]), "r"(b[1]));
}
__device__ __forceinline__ void cp16(uint32_t dst, const void* src) {
    asm volatile("cp.async.cg.shared.global [%0], [%1], 16;" :: "r"(dst), "l"(src));
}
#define CP_COMMIT() asm volatile("cp.async.commit_group;" ::: "memory")
#define CP_WAIT1()  asm volatile("cp.async.wait_group 1;" ::: "memory")
#define CP_WAIT0()  asm volatile("cp.async.wait_group 0;" ::: "memory")

// fp16 hi/lo pack: hi = rn(x), lo = rn(x - hi); hi+lo carries ~22 mantissa bits
__device__ __forceinline__ uint32_t pack_hi16(float x, float y, uint32_t& lo) {
    __half2 h, l;
    h.x = __float2half_rn(x);
    h.y = __float2half_rn(y);
    l.x = __float2half_rn(x - __half2float(h.x));
    l.y = __float2half_rn(y - __half2float(h.y));
    lo = *(uint32_t*)&l;
    return *(uint32_t*)&h;
}

// ---------------------------------------------------------------------------
// Conversion kernels
// ---------------------------------------------------------------------------
__global__ void convert_split16(const float4* __restrict__ in,
                                uint32_t* __restrict__ hi2, uint32_t* __restrict__ lo2,
                                int n4)
{
    int i = blockIdx.x * blockDim.x + threadIdx.x;
    if (i >= n4) return;
    float4 v = in[i];
    uint32_t l0, l1;
    uint32_t h0 = pack_hi16(v.x, v.y, l0);
    uint32_t h1 = pack_hi16(v.z, v.w, l1);
    hi2[2 * i] = h0; hi2[2 * i + 1] = h1;
    lo2[2 * i] = l0; lo2[2 * i + 1] = l1;
}

// W[K][N] row-major -> T[N][K] fp16 hi (transpose)
__global__ __launch_bounds__(256) void wt_convert16(
    const float* __restrict__ W, __half* __restrict__ Th, int K, int N)
{
    __shared__ float tile[32][33];
    const int n0 = blockIdx.x * 32, k0 = blockIdx.y * 32;
    const int tx = threadIdx.x & 31, ty = threadIdx.x >> 5;
    #pragma unroll
    for (int r = 0; r < 32; r += 8)
        tile[ty + r][tx] = W[(size_t)(k0 + ty + r) * N + n0 + tx];
    __syncthreads();
    #pragma unroll
    for (int r = 0; r < 32; r += 8) {
        const int n = n0 + ty + r, k = k0 + tx;
        Th[(size_t)n * K + k] = __float2half_rn(tile[tx][ty + r]);
    }
}

// ---------------------------------------------------------------------------
// fp16x2 GEMM: C[M,N] = (Ah+Al)[M,K] @ Bh[N,K]^T + bias.
// 128x128 tile, BK=32, 256 thr = 8 warps (2m x 4n), warp 64x32.
// 3-stage cp.async pipeline, ONE __syncthreads per k-iter.
// Stage = AH(8K) AL(8K) BH(8K) = 24KB; 3 stages = 72KB.
// 8x8-b16 tiles contiguous (128B) for conflict-free LDSM.
// ---------------------------------------------------------------------------
#define STG 24576
#define GEMM_SMEM_BYTES (3 * STG)   // 73728
#define NCHUNK (KDIM / 32)          // 32

__global__ __launch_bounds__(256) void gemm_f16x2(
    const __half* __restrict__ Agh, const __half* __restrict__ Agl,
    const __half* __restrict__ Bgh,
    const float* __restrict__ bias, float* __restrict__ Cf,
    __half* __restrict__ Cbh, __half* __restrict__ Cbl, int N)
{
    extern __shared__ __align__(1024) char smem[];
    const uint32_t sbase = smem_u32(smem);
    const int tid = threadIdx.x, lane = tid & 31, warp = tid >> 5;
    const int wm = warp & 1, wn = warp >> 1;
    const int brow = blockIdx.y * 128, bcol = blockIdx.x * 128;

    float acc[4][4][4] = {};

    auto stage = [&](int kt, int buf) {
        const int k0 = kt * 32;
        const uint32_t b0 = sbase + buf * STG;
        #pragma unroll
        for (int p = 0; p < 2; ++p) {
            const int idx = tid + p * 256;
            const int r = idx & 127, kc = idx >> 7;
            const uint32_t soff = (uint32_t)(((r >> 3) * 4 + kc) * 128 + (r & 7) * 16);
            const size_t ga = (size_t)(brow + r) * KDIM + k0 + kc * 8;
            const size_t gb = (size_t)(bcol + r) * KDIM + k0 + kc * 8;
            cp16(b0 + soff,         Agh + ga);
            cp16(b0 + 8192 + soff,  Agl + ga);
            cp16(b0 + 16384 + soff, Bgh + gb);
        }
    };

    auto compute = [&](int buf) {
        const uint32_t b0 = sbase + buf * STG;
        const int g = lane >> 3, row = lane & 7;
        #pragma unroll
        for (int s = 0; s < 2; ++s) {
            uint32_t aH[4][4], aL[4][4], bH[2][4];
            #pragma unroll
            for (int mi = 0; mi < 4; ++mi) {
                const int mt0 = wm * 8 + mi * 2;
                const uint32_t tile = (uint32_t)((mt0 + (g & 1)) * 4 + 2 * s + (g >> 1));
                const uint32_t addr = b0 + tile * 128 + row * 16;
                ldsm4(aH[mi], addr);
                ldsm4(aL[mi], addr + 8192);
            }
            #pragma unroll
            for (int hf = 0; hf < 2; ++hf) {
                const int ng = wn * 4 + hf * 2;
                const uint32_t tile = (uint32_t)((ng + (g >> 1)) * 4 + 2 * s + (g & 1));
                ldsm4(bH[hf], b0 + 16384 + tile * 128 + row * 16);
            }
            #pragma unroll
            for (int mi = 0; mi < 4; ++mi)
                #pragma unroll
                for (int nj = 0; nj < 4; ++nj) {
                    const uint32_t* bh = &bH[nj >> 1][(nj & 1) * 2];
                    mma_f16(acc[mi][nj], aH[mi], bh);
                    mma_f16(acc[mi][nj], aL[mi], bh);
                }
        }
    };

    stage(0, 0); CP_COMMIT();
    stage(1, 1); CP_COMMIT();
    for (int kt = 0; kt < NCHUNK; ++kt) {
        if (kt + 1 < NCHUNK) { CP_WAIT1(); } else { CP_WAIT0(); }
        __syncthreads();   // group kt visible to all; prev compute on (kt+2)%3 done
        if (kt + 2 < NCHUNK) { stage(kt + 2, (kt + 2) % 3); CP_COMMIT(); }
        compute(kt % 3);
    }

    const int r4 = lane >> 2, c2 = (lane & 3) * 2;
    #pragma unroll
    for (int mi = 0; mi < 4; ++mi) {
        const int row = brow + wm * 64 + mi * 16 + r4;
        #pragma unroll
        for (int nj = 0; nj < 4; ++nj) {
            const int col = bcol + wn * 32 + nj * 8 + c2;
            const float b0 = __ldg(&bias[col]), b1 = __ldg(&bias[col + 1]);
            const float x0 = acc[mi][nj][0] + b0, y0 = acc[mi][nj][1] + b1;
            const float x1 = acc[mi][nj][2] + b0, y1 = acc[mi][nj][3] + b1;
            if (Cf) {
                *(float2*)(Cf + (size_t)row * N + col) = make_float2(x0, y0);
                *(float2*)(Cf + (size_t)(row + 8) * N + col) = make_float2(x1, y1);
            } else {
                uint32_t l0, l1;
                const uint32_t h0 = pack_hi16(x0, y0, l0);
                const uint32_t h1 = pack_hi16(x1, y1, l1);
                *(uint32_t*)(Cbh + (size_t)row * N + col) = h0;
                *(uint32_t*)(Cbl + (size_t)row * N + col) = l0;
                *(uint32_t*)(Cbh + (size_t)(row + 8) * N + col) = h1;
                *(uint32_t*)(Cbl + (size_t)(row + 8) * N + col) = l1;
            }
        }
    }
}

// ---------------------------------------------------------------------------
// Flash attention, fp16x2 mma. Grid (L/128, H, B), 256 thr = 8 warps.
// Warp w owns q rows [16w, 16w+16). Key chunks of 64.
// A-side split: Q hi/lo, P hi/lo. B-side single: K hi, V hi.
// SMEM (80KB): QH 0(16K) QL 16K | KH 32K(8K) | VH 40K(8K)
//              PH 48K(16K = 8 warps x 2K) PL 64K
// ---------------------------------------------------------------------------
#define AS_QH 0
#define AS_QL 16384
#define AS_KH 32768
#define AS_VH 40960
#define AS_PH 49152
#define AS_PL 65536
#define ATTN_SMEM_BYTES 81920

__global__ __launch_bounds__(256) void attn_f16x2(
    const __half* __restrict__ qh, const __half* __restrict__ ql,
    __half* __restrict__ oh, __half* __restrict__ ol)
{
    extern __shared__ __align__(1024) char smem[];
    const uint32_t sbase = smem_u32(smem);
    const int b = blockIdx.z, h = blockIdx.y, q0 = blockIdx.x * 128;
    const int tid = threadIdx.x, lane = tid & 31, warp = tid >> 5;
    const int g = lane >> 3, lrow = lane & 7;
    const size_t hbase = (size_t)h * (3 * DK_);

    // ---- stage Q (128 x 64 hi/lo) ----
    for (int idx = tid; idx < 1024; idx += 256) {
        const int r = idx >> 3, c = idx & 7;
        const uint32_t soff = (uint32_t)(((r >> 3) * 8 + c) * 128 + (r & 7) * 16);
        const size_t ga = ((size_t)b * L_ + q0 + r) * QKV_N + hbase + c * 8;
        cp16(sbase + AS_QH + soff, qh + ga);
        cp16(sbase + AS_QL + soff, ql + ga);
    }
    CP_COMMIT();

    float oacc[8][4] = {};
    float m0 = -INFINITY, m1 = -INFINITY, l0 = 0.f, l1 = 0.f;
    const float scale = 0.125f;

    for (int kc = 0; kc < L_; kc += 64) {
        __syncthreads();   // all warps done reading prev K/V
        // ---- stage K,V chunk (64 x 64, hi only) ----
        for (int idx = tid; idx < 512; idx += 256) {
            const int r = idx >> 3, c = idx & 7;
            const uint32_t soff = (uint32_t)(((r >> 3) * 8 + c) * 128 + (r & 7) * 16);
            const size_t ga = ((size_t)b * L_ + kc + r) * QKV_N + hbase + c * 8;
            cp16(sbase + AS_KH + soff, qh + ga + DK_);
            cp16(sbase + AS_VH + soff, qh + ga + 2 * DK_);
        }
        CP_COMMIT();
        CP_WAIT0();
        __syncthreads();

        // ---- S = (Qh+Ql) K^T : 16(q) x 64(key), k = 64(d) ----
        float sacc[8][4] = {};
        #pragma unroll
        for (int s = 0; s < 4; ++s) {
            uint32_t aH[4], aL[4];
            {
                const int mt0 = warp * 2;
                const uint32_t tile = (uint32_t)((mt0 + (g & 1)) * 8 + 2 * s + (g >> 1));
                const uint32_t addr = sbase + AS_QH + tile * 128 + lrow * 16;
                ldsm4(aH, addr);
                ldsm4(aL, addr + (AS_QL - AS_QH));
            }
            #pragma unroll
            for (int hf = 0; hf < 4; ++hf) {
                uint32_t bH[4];
                const int ng = hf * 2;
                const uint32_t tile = (uint32_t)((ng + (g >> 1)) * 8 + 2 * s + (g & 1));
                ldsm4(bH, sbase + AS_KH + tile * 128 + lrow * 16);
                #pragma unroll
                for (int q = 0; q < 2; ++q) {
                    float* c = sacc[ng + q];
                    mma_f16(c, aH, &bH[q * 2]);
                    mma_f16(c, aL, &bH[q * 2]);
                }
            }
        }

        // ---- online softmax (row0 = regs 0,1 ; row1 = regs 2,3) ----
        {
            float mloc = -INFINITY;
            #pragma unroll
            for (int nj = 0; nj < 8; ++nj) {
                sacc[nj][0] *= scale; sacc[nj][1] *= scale;
                mloc = fmaxf(mloc, fmaxf(sacc[nj][0], sacc[nj][1]));
            }
            mloc = fmaxf(mloc, __shfl_xor_sync(0xffffffffu, mloc, 1));
            mloc = fmaxf(mloc, __shfl_xor_sync(0xffffffffu, mloc, 2));
            const float mnew = fmaxf(m0, mloc);
            const float corr = __expf(m0 - mnew);
            m0 = mnew;
            float lsum = 0.f;
            #pragma unroll
            for (int nj = 0; nj < 8; ++nj) {
                const float p0 = __expf(sacc[nj][0] - mnew);
                const float p1 = __expf(sacc[nj][1] - mnew);
                sacc[nj][0] = p0; sacc[nj][1] = p1;
                lsum += p0 + p1;
            }
            lsum += __shfl_xor_sync(0xffffffffu, lsum, 1);
            lsum += __shfl_xor_sync(0xffffffffu, lsum, 2);
            l0 = l0 * corr + lsum;
            #pragma unroll
            for (int nj = 0; nj < 8; ++nj) { oacc[nj][0] *= corr; oacc[nj][1] *= corr; }
        }
        {
            float mloc = -INFINITY;
            #pragma unroll
            for (int nj = 0; nj < 8; ++nj) {
                sacc[nj][2] *= scale; sacc[nj][3] *= scale;
                mloc = fmaxf(mloc, fmaxf(sacc[nj][2], sacc[nj][3]));
            }
            mloc = fmaxf(mloc, __shfl_xor_sync(0xffffffffu, mloc, 1));
            mloc = fmaxf(mloc, __shfl_xor_sync(0xffffffffu, mloc, 2));
            const float mnew = fmaxf(m1, mloc);
            const float corr = __expf(m1 - mnew);
            m1 = mnew;
            float lsum = 0.f;
            #pragma unroll
            for (int nj = 0; nj < 8; ++nj) {
                const float p0 = __expf(sacc[nj][2] - mnew);
                const float p1 = __expf(sacc[nj][3] - mnew);
                sacc[nj][2] = p0; sacc[nj][3] = p1;
                lsum += p0 + p1;
            }
            lsum += __shfl_xor_sync(0xffffffffu, lsum, 1);
            lsum += __shfl_xor_sync(0xffffffffu, lsum, 2);
            l1 = l1 * corr + lsum;
            #pragma unroll
            for (int nj = 0; nj < 8; ++nj) { oacc[nj][2] *= corr; oacc[nj][3] *= corr; }
        }

        // ---- store P (16 x 64) hi/lo into per-warp tile region ----
        {
            const int r4 = lane >> 2, cb = 4 * (lane & 3);
            #pragma unroll
            for (int nj = 0; nj < 8; ++nj) {
                uint32_t plo;
                const uint32_t ph0 = pack_hi16(sacc[nj][0], sacc[nj][1], plo);
                const uint32_t off0 = (uint32_t)((0 * 8 + nj) * 128 + r4 * 16 + cb);
                *(uint32_t*)(smem + AS_PH + warp * 2048 + off0) = ph0;
                *(uint32_t*)(smem + AS_PL + warp * 2048 + off0) = plo;
                const uint32_t ph1 = pack_hi16(sacc[nj][2], sacc[nj][3], plo);
                const uint32_t off1 = (uint32_t)((1 * 8 + nj) * 128 + r4 * 16 + cb);
                *(uint32_t*)(smem + AS_PH + warp * 2048 + off1) = ph1;
                *(uint32_t*)(smem + AS_PL + warp * 2048 + off1) = plo;
            }
        }
        __syncwarp();

        // ---- O += (Ph+Pl) V : 16(q) x 64(d), k = 64(key) ----
        #pragma unroll
        for (int s = 0; s < 4; ++s) {
            uint32_t aH[4], aL[4];
            {
                const uint32_t tile = (uint32_t)((g & 1) * 8 + 2 * s + (g >> 1));
                const uint32_t addr = sbase + AS_PH + warp * 2048 + tile * 128 + lrow * 16;
                ldsm4(aH, addr);
                ldsm4(aL, addr + (AS_PL - AS_PH));
            }
            #pragma unroll
            for (int hf = 0; hf < 4; ++hf) {
                uint32_t bH[4];
                const int dt = hf * 2;
                const uint32_t tile = (uint32_t)((2 * s + (g & 1)) * 8 + dt + (g >> 1));
                ldsm4t(bH, sbase + AS_VH + tile * 128 + lrow * 16);
                #pragma unroll
                for (int q = 0; q < 2; ++q) {
                    float* c = oacc[dt + q];
                    mma_f16(c, aH, &bH[q * 2]);
                    mma_f16(c, aL, &bH[q * 2]);
                }
            }
        }
    }

    // ---- epilogue: normalize, split, write fp16 hi/lo [token][HD] ----
    const float inv0 = 1.f / l0, inv1 = 1.f / l1;
    const int r4 = lane >> 2, c2 = 2 * (lane & 3);
    const size_t row0 = (size_t)b * L_ + q0 + warp * 16 + r4;
    #pragma unroll
    for (int nj = 0; nj < 8; ++nj) {
        const int col = h * DK_ + nj * 8 + c2;
        uint32_t lo;
        const uint32_t h0 = pack_hi16(oacc[nj][0] * inv0, oacc[nj][1] * inv0, lo);
        *(uint32_t*)(oh + row0 * HD_ + col) = h0;
        *(uint32_t*)(ol + row0 * HD_ + col) = lo;
        const uint32_t h1 = pack_hi16(oacc[nj][2] * inv1, oacc[nj][3] * inv1, lo);
        *(uint32_t*)(oh + (row0 + 8) * HD_ + col) = h1;
        *(uint32_t*)(ol + (row0 + 8) * HD_ + col) = lo;
    }
}

// ---------------------------------------------------------------------------
// Launch
// ---------------------------------------------------------------------------
extern "C" void kernel_launch(void* const* d_in, const int* in_sizes, int n_in,
                              void* d_out, int out_size)
{
    const float* X    = (const float*)d_in[0];
    const float* Wqkv = (const float*)d_in[1];
    const float* bqkv = (const float*)d_in[2];
    const float* Wfc  = (const float*)d_in[3];
    const float* bfc  = (const float*)d_in[4];
    float* out = (float*)d_out;

    __half *Xh, *Xl, *Wqh, *Wfh, *qkvh, *qkvl, *Ath, *Atl;
    cudaGetSymbolAddress((void**)&Xh, g_Xh);
    cudaGetSymbolAddress((void**)&Xl, g_Xl);
    cudaGetSymbolAddress((void**)&Wqh, g_Wqh);
    cudaGetSymbolAddress((void**)&Wfh, g_Wfh);
    cudaGetSymbolAddress((void**)&qkvh, g_qkvh);
    cudaGetSymbolAddress((void**)&qkvl, g_qkvl);
    cudaGetSymbolAddress((void**)&Ath, g_Ath);
    cudaGetSymbolAddress((void**)&Atl, g_Atl);

    cudaFuncSetAttribute(gemm_f16x2,
                         cudaFuncAttributeMaxDynamicSharedMemorySize, GEMM_SMEM_BYTES);
    cudaFuncSetAttribute(attn_f16x2,
                         cudaFuncAttributeMaxDynamicSharedMemorySize, ATTN_SMEM_BYTES);

    // 0) conversions
    {
        const int n4 = MTOK * E_ / 4;
        convert_split16<<<(n4 + 255) / 256, 256>>>(
            (const float4*)X, (uint32_t*)Xh, (uint32_t*)Xl, n4);
        wt_convert16<<<dim3(QKV_N / 32, KDIM / 32), 256>>>(Wqkv, Wqh, KDIM, QKV_N);
        wt_convert16<<<dim3(HD_ / 32, KDIM / 32), 256>>>(Wfc, Wfh, KDIM, HD_);
    }

    // 1) QKV = X @ Wqkv + b -> fp16 hi/lo
    gemm_f16x2<<<dim3(QKV_N / 128, MTOK / 128), 256, GEMM_SMEM_BYTES>>>(
        Xh, Xl, Wqh, bqkv, nullptr, qkvh, qkvl, QKV_N);

    // 2) attention -> fp16 hi/lo
    attn_f16x2<<<dim3(L_ / 128, H_, B_), 256, ATTN_SMEM_BYTES>>>(
        qkvh, qkvl, Ath, Atl);

    // 3) FC -> fp32 out
    gemm_f16x2<<<dim3(HD_ / 128, MTOK / 128), 256, GEMM_SMEM_BYTES>>>(
        Ath, Atl, Wfh, bfc, out, nullptr, nullptr, HD_);
}